// round 12
// baseline (speedup 1.0000x reference)
#include <cuda_runtime.h>
#include <cuda_bf16.h>
#include <cfloat>
#include <cstdint>

// Problem shape (fixed by the dataset)
#define B_Q 2048
#define N_S 32768
#define D_K 256
#define N_CLS 100

// Phase A: pure bf16 GEMM, K = 256
#define KP 256
#define NKCH (KP / 64)             // 4 K-chunks of 64 bf16
#define TILE_M 128
#define TILE_N 256
#define GRID_M (B_Q / TILE_M)      // 16
#define GRID_N (N_S / TILE_N)      // 128
#define NTHREADS 512
#define STAGES 4
#define A_STAGE 16384              // 128 x 128B
#define B_STAGE 32768              // 256 x 128B
#define STAGE_BYTES (A_STAGE + B_STAGE)   // 48 KB
#define ROWB 128
#define GROWB (KP * 2)             // 512 bytes per global row

// ---- device global scratch (allocation-free contract) ----
__device__ __nv_bfloat16 g_A[(size_t)B_Q * KP];       // 1 MB
__device__ __nv_bfloat16 g_B[(size_t)N_S * KP];       // 16.8 MB
__device__ float g_score[(size_t)B_Q * N_S];          // 268 MB approx scores
__device__ float g_s2[N_S];
__device__ float g_xs2[B_Q];
__device__ int   g_ymax2_bits;                        // atomicMax over positive floats
__device__ float g_pv[(size_t)B_Q * GRID_N];          // per-(q,tile) approx min
__device__ float g_amin[B_Q];                         // global approx min per q
__device__ int   g_labmode;                           // 1 = int64 storage

// ---------------------------------------------------------------------------
// helpers
// ---------------------------------------------------------------------------
__device__ __forceinline__ uint32_t smem_u32(const void* p) {
    uint32_t a;
    asm("{ .reg .u64 t; cvta.to.shared.u64 t, %1; cvt.u32.u64 %0, t; }"
        : "=r"(a) : "l"(p));
    return a;
}
__device__ __forceinline__ void cp16(uint32_t dst, const void* src) {
    asm volatile("cp.async.cg.shared.global [%0], [%1], 16;"
                 :: "r"(dst), "l"(src) : "memory");
}
__device__ __forceinline__ void cp_commit() {
    asm volatile("cp.async.commit_group;" ::: "memory");
}
template <int N> __device__ __forceinline__ void cp_wait() {
    asm volatile("cp.async.wait_group %0;" :: "n"(N) : "memory");
}
__device__ __forceinline__ void ldsm4(uint32_t& r0, uint32_t& r1,
                                      uint32_t& r2, uint32_t& r3, uint32_t a) {
    asm volatile("ldmatrix.sync.aligned.m8n8.x4.shared.b16 {%0,%1,%2,%3}, [%4];"
                 : "=r"(r0), "=r"(r1), "=r"(r2), "=r"(r3) : "r"(a));
}
__device__ __forceinline__ void mma16816(float* c, const uint32_t* a,
                                         const uint32_t* b) {
    asm volatile(
        "mma.sync.aligned.m16n8k16.row.col.f32.bf16.bf16.f32 "
        "{%0,%1,%2,%3}, {%4,%5,%6,%7}, {%8,%9}, {%0,%1,%2,%3};"
        : "+f"(c[0]), "+f"(c[1]), "+f"(c[2]), "+f"(c[3])
        : "r"(a[0]), "r"(a[1]), "r"(a[2]), "r"(a[3]), "r"(b[0]), "r"(b[1]));
}
__device__ __forceinline__ uint32_t swz(uint32_t row, uint32_t colb) {
    return row * ROWB + (colb ^ ((row & 7u) << 4));
}

// ---------------------------------------------------------------------------
// Prologue 1: x -> bf16, xs2; also resets ymax accumulator (runs first)
// ---------------------------------------------------------------------------
__global__ void convert_x_kernel(const float* __restrict__ x) {
    __shared__ float red[8];
    int q = blockIdx.x, d = threadIdx.x;
    if (q == 0 && d == 0) g_ymax2_bits = 0;
    float v = x[(size_t)q * D_K + d];
    g_A[(size_t)q * KP + d] = __float2bfloat16(v);
    float s = v * v;
    #pragma unroll
    for (int off = 16; off > 0; off >>= 1) s += __shfl_down_sync(0xffffffffu, s, off);
    if ((d & 31) == 0) red[d >> 5] = s;
    __syncthreads();
    if (d == 0) {
        float t = 0.f;
        #pragma unroll
        for (int i = 0; i < 8; i++) t += red[i];
        g_xs2[q] = t;
    }
}

// ---------------------------------------------------------------------------
// Prologue 2: support -> bf16, s2 (fp32), global max ||y||^2
// ---------------------------------------------------------------------------
__global__ void convert_s_kernel(const float* __restrict__ sup) {
    __shared__ float red[8];
    int n = blockIdx.x, d = threadIdx.x;
    float v = sup[(size_t)n * D_K + d];
    g_B[(size_t)n * KP + d] = __float2bfloat16(v);
    float s = v * v;
    #pragma unroll
    for (int off = 16; off > 0; off >>= 1) s += __shfl_down_sync(0xffffffffu, s, off);
    if ((d & 31) == 0) red[d >> 5] = s;
    __syncthreads();
    if (d == 0) {
        float t = 0.f;
        #pragma unroll
        for (int i = 0; i < 8; i++) t += red[i];
        g_s2[n] = t;
        atomicMax(&g_ymax2_bits, __float_as_int(t));   // t > 0: bit order = value order
    }
}

// ---------------------------------------------------------------------------
// Phase A: bf16 HMMA GEMM M128 x N256 x K256; store approx scores + tile mins
// grid (128, 16), 512 threads (16 warps, 4x4, warp tile 32x64)
// ---------------------------------------------------------------------------
__global__ __launch_bounds__(NTHREADS, 1)
void knn_approx_kernel() {
    extern __shared__ char smem[];
    const uint32_t sb = smem_u32(smem);
    __shared__ float s_s2[TILE_N];
    __shared__ float spv[TILE_M][4];

    const int tid = threadIdx.x, wid = tid >> 5, lane = tid & 31;
    const int warp_m = wid & 3, warp_n = wid >> 2;
    const int n0 = blockIdx.x * TILE_N, m0 = blockIdx.y * TILE_M;

    if (tid < TILE_N) s_s2[tid] = g_s2[n0 + tid];

    const char* gA = (const char*)g_A + (size_t)m0 * GROWB;
    const char* gB = (const char*)g_B + (size_t)n0 * GROWB;

    auto load_chunk = [&](int kc, int stg) {
        uint32_t sA = sb + stg * STAGE_BYTES;
        uint32_t sB = sA + A_STAGE;
        size_t colb = (size_t)kc * ROWB;
        #pragma unroll
        for (int i = 0; i < 2; i++) {
            int idx = tid + i * NTHREADS;
            int r = idx >> 3, p = (idx & 7) * 16;
            cp16(sA + swz(r, p), gA + (size_t)r * GROWB + colb + p);
        }
        #pragma unroll
        for (int i = 0; i < 4; i++) {
            int idx = tid + i * NTHREADS;
            int r = idx >> 3, p = (idx & 7) * 16;
            cp16(sB + swz(r, p), gB + (size_t)r * GROWB + colb + p);
        }
        cp_commit();
    };

    float acc[2][8][4];
    #pragma unroll
    for (int mt = 0; mt < 2; mt++)
        #pragma unroll
        for (int nb = 0; nb < 8; nb++)
            #pragma unroll
            for (int i = 0; i < 4; i++) acc[mt][nb][i] = 0.f;

    const uint32_t a_row = (uint32_t)(warp_m * 32 + (lane & 15));
    const uint32_t a_sub = (uint32_t)((lane >> 4) * 16);
    const uint32_t b_row = (uint32_t)(warp_n * 64 + (lane & 7) + ((lane >> 4) << 3));
    const uint32_t b_sub = (uint32_t)(((lane >> 3) & 1) * 16);

    load_chunk(0, 0);
    load_chunk(1, 1);
    load_chunk(2, 2);

    for (int k = 0; k < NKCH; k++) {
        if (k < NKCH - 2)       cp_wait<2>();
        else if (k == NKCH - 2) cp_wait<1>();
        else                    cp_wait<0>();
        __syncthreads();
        if (k + 3 < NKCH) load_chunk(k + 3, (k + 3) & 3);

        uint32_t sA = sb + (k & 3) * STAGE_BYTES;
        uint32_t sB = sA + A_STAGE;
        #pragma unroll
        for (int ks = 0; ks < 4; ks++) {
            uint32_t colA = (uint32_t)(ks * 32) + a_sub;
            uint32_t colB = (uint32_t)(ks * 32) + b_sub;
            uint32_t a[2][4], b[8][2];
            #pragma unroll
            for (int mt = 0; mt < 2; mt++)
                ldsm4(a[mt][0], a[mt][1], a[mt][2], a[mt][3],
                      sA + swz(a_row + mt * 16, colA));
            #pragma unroll
            for (int nb2 = 0; nb2 < 4; nb2++)
                ldsm4(b[nb2 * 2][0], b[nb2 * 2][1],
                      b[nb2 * 2 + 1][0], b[nb2 * 2 + 1][1],
                      sB + swz(b_row + nb2 * 16, colB));
            #pragma unroll
            for (int mt = 0; mt < 2; mt++)
                #pragma unroll
                for (int nb = 0; nb < 8; nb++)
                    mma16816(acc[mt][nb], a[mt], b[nb]);
        }
    }

    // Epilogue: score = s2 - 2*dot; store all scores; track per-row min value
    float bv[2][2] = {{FLT_MAX, FLT_MAX}, {FLT_MAX, FLT_MAX}};
    #pragma unroll
    for (int mt = 0; mt < 2; mt++)
        #pragma unroll
        for (int rh = 0; rh < 2; rh++) {
            int row = warp_m * 32 + mt * 16 + rh * 8 + (lane >> 2);
            float* srow = g_score + (size_t)(m0 + row) * N_S + n0;
            #pragma unroll
            for (int nb = 0; nb < 8; nb++) {
                int col = warp_n * 64 + nb * 8 + 2 * (lane & 3);
                float sc0 = fmaf(-2.0f, acc[mt][nb][rh * 2 + 0], s_s2[col]);
                float sc1 = fmaf(-2.0f, acc[mt][nb][rh * 2 + 1], s_s2[col + 1]);
                *(float2*)(srow + col) = make_float2(sc0, sc1);
                float m = fminf(sc0, sc1);
                if (m < bv[mt][rh]) bv[mt][rh] = m;
            }
        }

    #pragma unroll
    for (int mt = 0; mt < 2; mt++)
        #pragma unroll
        for (int rh = 0; rh < 2; rh++) {
            float v = bv[mt][rh];
            #pragma unroll
            for (int msk = 1; msk <= 2; msk <<= 1)
                v = fminf(v, __shfl_xor_sync(0xffffffffu, v, msk));
            if ((lane & 3) == 0) {
                int row = warp_m * 32 + mt * 16 + rh * 8 + (lane >> 2);
                spv[row][warp_n] = v;
            }
        }
    __syncthreads();

    if (tid < TILE_M) {
        float v = fminf(fminf(spv[tid][0], spv[tid][1]),
                        fminf(spv[tid][2], spv[tid][3]));
        g_pv[(size_t)(m0 + tid) * GRID_N + blockIdx.x] = v;
    }
}

// ---------------------------------------------------------------------------
// Reduce: global approx min per query; block 0 also detects label storage
// ---------------------------------------------------------------------------
__global__ void reduce_kernel(const int* __restrict__ lab32) {
    __shared__ float sv[GRID_N];
    const int b = blockIdx.x, t = threadIdx.x;
    sv[t] = g_pv[(size_t)b * GRID_N + t];
    __syncthreads();
    #pragma unroll
    for (int s = GRID_N / 2; s > 0; s >>= 1) {
        if (t < s) sv[t] = fminf(sv[t], sv[t + s]);
        __syncthreads();
    }
    if (t == 0) {
        g_amin[b] = sv[0];
        if (b == 0) {
            int hiOr = 0;
            #pragma unroll
            for (int w = 1; w < 64; w += 2) hiOr |= lab32[w];
            g_labmode = (hiOr == 0) ? 1 : 0;   // 1 = int64 storage
        }
    }
}

// ---------------------------------------------------------------------------
// Phase B: warp-per-query scan of approx scores; exact fp32 rescore of
// candidates under (amin + margin); fused label gather + one-hot write.
// Margin: |approx-exact| <= 2*2^-8*||x||*||y||  =>  M = 0.02*||x||*ymax + 0.25
// ---------------------------------------------------------------------------
__global__ __launch_bounds__(256)
void scan_kernel(const float* __restrict__ x, const float* __restrict__ sup,
                 const int* __restrict__ lab32, float* __restrict__ out) {
    const int wid = threadIdx.x >> 5, lane = threadIdx.x & 31;
    const int q = blockIdx.x * 8 + wid;

    // preload x row: 8 fp32 per lane (dims 4*lane.. and 128+4*lane..)
    const float4* xrow = (const float4*)(x + (size_t)q * D_K);
    float4 xv0 = xrow[lane];
    float4 xv1 = xrow[lane + 32];

    float ymax2 = __int_as_float(g_ymax2_bits);
    float thresh = g_amin[q] + 0.02f * sqrtf(g_xs2[q] * ymax2) + 0.25f;

    const float* srow = g_score + (size_t)q * N_S;
    float bestV = FLT_MAX; int bestN = 0;

    for (int base = 0; base < N_S; base += 128) {
        float4 s4 = *(const float4*)(srow + base + lane * 4);
        unsigned m = 0;
        if (s4.x <= thresh) m |= 1;
        if (s4.y <= thresh) m |= 2;
        if (s4.z <= thresh) m |= 4;
        if (s4.w <= thresh) m |= 8;
        unsigned bal = __ballot_sync(0xffffffffu, m != 0);
        while (bal) {
            int src = __ffs(bal) - 1; bal &= bal - 1;
            unsigned mm = __shfl_sync(0xffffffffu, m, src);
            #pragma unroll
            for (int c = 0; c < 4; c++) {
                if (mm & (1u << c)) {
                    int n = base + src * 4 + c;
                    const float4* yrow = (const float4*)(sup + (size_t)n * D_K);
                    float4 y0 = yrow[lane], y1 = yrow[lane + 32];
                    float d = xv0.x * y0.x + xv0.y * y0.y + xv0.z * y0.z + xv0.w * y0.w
                            + xv1.x * y1.x + xv1.y * y1.y + xv1.z * y1.z + xv1.w * y1.w;
                    #pragma unroll
                    for (int off = 16; off > 0; off >>= 1)
                        d += __shfl_xor_sync(0xffffffffu, d, off);
                    float sc = g_s2[n] - 2.0f * d;
                    if (sc < bestV || (sc == bestV && n < bestN)) { bestV = sc; bestN = n; }
                }
            }
        }
    }

    // label gather (uniform across warp: bestV/bestN identical on all lanes)
    int lbl = (g_labmode == 1) ? lab32[2 * bestN] : lab32[bestN];
    #pragma unroll
    for (int c = lane; c < N_CLS; c += 32)
        out[(size_t)q * N_CLS + c] = (c == lbl) ? 1.0f : 0.0f;
}

// ---------------------------------------------------------------------------
extern "C" void kernel_launch(void* const* d_in, const int* in_sizes, int n_in,
                              void* d_out, int out_size) {
    const float* x     = nullptr;
    const float* sup   = nullptr;
    const int*   lab32 = nullptr;
    for (int i = 0; i < n_in; i++) {
        long long sz = in_sizes[i];
        if (sz == 524288LL || sz == 2097152LL)         x     = (const float*)d_in[i];
        else if (sz == 8388608LL || sz == 33554432LL)  sup   = (const float*)d_in[i];
        else if (sz == 32768LL || sz == 65536LL ||
                 sz == 131072LL || sz == 262144LL)     lab32 = (const int*)d_in[i];
    }
    if (!x)     x     = (const float*)d_in[0];
    if (!sup)   sup   = (const float*)d_in[1];
    if (!lab32) lab32 = (const int*)d_in[2];
    float* out = (float*)d_out;

    static bool attr_set = false;
    if (!attr_set) {
        cudaFuncSetAttribute(knn_approx_kernel,
                             cudaFuncAttributeMaxDynamicSharedMemorySize,
                             STAGES * STAGE_BYTES);
        attr_set = true;
    }

    convert_x_kernel<<<B_Q, D_K>>>(x);
    convert_s_kernel<<<N_S, D_K>>>(sup);

    dim3 grid(GRID_N, GRID_M);   // 128 x 16
    knn_approx_kernel<<<grid, NTHREADS, STAGES * STAGE_BYTES>>>();

    reduce_kernel<<<B_Q, GRID_N>>>(lab32);

    scan_kernel<<<B_Q / 8, 256>>>(x, sup, lab32, out);
}

// round 14
// speedup vs baseline: 1.7303x; 1.7303x over previous
#include <cuda_runtime.h>
#include <cuda_bf16.h>
#include <cfloat>
#include <cstdint>

// Problem shape (fixed by the dataset)
#define B_Q 2048
#define N_S 32768
#define D_K 256
#define N_CLS 100

// Phase A: pure bf16 GEMM, K = 256
#define KP 256
#define NKCH (KP / 64)             // 4 K-chunks of 64 bf16
#define TILE_M 128
#define TILE_N 256
#define GRID_M (B_Q / TILE_M)      // 16
#define GRID_N (N_S / TILE_N)      // 128
#define NTHREADS 512
#define STAGES 4
#define A_STAGE 16384              // 128 x 128B
#define B_STAGE 32768              // 256 x 128B
#define STAGE_BYTES (A_STAGE + B_STAGE)   // 48 KB
#define ROWB 128
#define GROWB (KP * 2)             // 512 bytes per global row
#define SROWW 132                  // staging row stride in words (pad: bank-safe)

// ---- device global scratch (allocation-free contract) ----
__device__ __nv_bfloat16 g_A[(size_t)B_Q * KP];        // 1 MB
__device__ __nv_bfloat16 g_B[(size_t)N_S * KP];        // 16.8 MB
__device__ __nv_bfloat16 g_score[(size_t)B_Q * N_S];   // 134 MB approx scores
__device__ float g_s2[N_S];
__device__ float g_xs2[B_Q];
__device__ int   g_ymax2_bits;                         // atomicMax over positive floats
__device__ float g_pv[(size_t)B_Q * GRID_N];           // per-(q,tile) fp32 approx min
__device__ float g_amin[B_Q];                          // global approx min per q
__device__ int   g_labmode;                            // 1 = int64 storage

// ---------------------------------------------------------------------------
// helpers
// ---------------------------------------------------------------------------
__device__ __forceinline__ uint32_t smem_u32(const void* p) {
    uint32_t a;
    asm("{ .reg .u64 t; cvta.to.shared.u64 t, %1; cvt.u32.u64 %0, t; }"
        : "=r"(a) : "l"(p));
    return a;
}
__device__ __forceinline__ void cp16(uint32_t dst, const void* src) {
    asm volatile("cp.async.cg.shared.global [%0], [%1], 16;"
                 :: "r"(dst), "l"(src) : "memory");
}
__device__ __forceinline__ void cp_commit() {
    asm volatile("cp.async.commit_group;" ::: "memory");
}
template <int N> __device__ __forceinline__ void cp_wait() {
    asm volatile("cp.async.wait_group %0;" :: "n"(N) : "memory");
}
__device__ __forceinline__ void ldsm4(uint32_t& r0, uint32_t& r1,
                                      uint32_t& r2, uint32_t& r3, uint32_t a) {
    asm volatile("ldmatrix.sync.aligned.m8n8.x4.shared.b16 {%0,%1,%2,%3}, [%4];"
                 : "=r"(r0), "=r"(r1), "=r"(r2), "=r"(r3) : "r"(a));
}
__device__ __forceinline__ void mma16816(float* c, const uint32_t* a,
                                         const uint32_t* b) {
    asm volatile(
        "mma.sync.aligned.m16n8k16.row.col.f32.bf16.bf16.f32 "
        "{%0,%1,%2,%3}, {%4,%5,%6,%7}, {%8,%9}, {%0,%1,%2,%3};"
        : "+f"(c[0]), "+f"(c[1]), "+f"(c[2]), "+f"(c[3])
        : "r"(a[0]), "r"(a[1]), "r"(a[2]), "r"(a[3]), "r"(b[0]), "r"(b[1]));
}
__device__ __forceinline__ uint32_t swz(uint32_t row, uint32_t colb) {
    return row * ROWB + (colb ^ ((row & 7u) << 4));
}

// ---------------------------------------------------------------------------
// Prologue 1: x -> bf16, xs2; also resets ymax accumulator (runs first)
// ---------------------------------------------------------------------------
__global__ void convert_x_kernel(const float* __restrict__ x) {
    __shared__ float red[8];
    int q = blockIdx.x, d = threadIdx.x;
    if (q == 0 && d == 0) g_ymax2_bits = 0;
    float v = x[(size_t)q * D_K + d];
    g_A[(size_t)q * KP + d] = __float2bfloat16(v);
    float s = v * v;
    #pragma unroll
    for (int off = 16; off > 0; off >>= 1) s += __shfl_down_sync(0xffffffffu, s, off);
    if ((d & 31) == 0) red[d >> 5] = s;
    __syncthreads();
    if (d == 0) {
        float t = 0.f;
        #pragma unroll
        for (int i = 0; i < 8; i++) t += red[i];
        g_xs2[q] = t;
    }
}

// ---------------------------------------------------------------------------
// Prologue 2: support -> bf16, s2 (fp32), global max ||y||^2
// ---------------------------------------------------------------------------
__global__ void convert_s_kernel(const float* __restrict__ sup) {
    __shared__ float red[8];
    int n = blockIdx.x, d = threadIdx.x;
    float v = sup[(size_t)n * D_K + d];
    g_B[(size_t)n * KP + d] = __float2bfloat16(v);
    float s = v * v;
    #pragma unroll
    for (int off = 16; off > 0; off >>= 1) s += __shfl_down_sync(0xffffffffu, s, off);
    if ((d & 31) == 0) red[d >> 5] = s;
    __syncthreads();
    if (d == 0) {
        float t = 0.f;
        #pragma unroll
        for (int i = 0; i < 8; i++) t += red[i];
        g_s2[n] = t;
        atomicMax(&g_ymax2_bits, __float_as_int(t));   // t > 0: bit order = value order
    }
}

// ---------------------------------------------------------------------------
// Phase A: bf16 HMMA GEMM M128 x N256 x K256; scores -> SMEM staging -> bf16
// coalesced store; per-(q,tile) fp32 min partials.
// grid (128, 16), 512 threads (16 warps, 4x4, warp tile 32x64)
// ---------------------------------------------------------------------------
__global__ __launch_bounds__(NTHREADS, 1)
void knn_approx_kernel() {
    extern __shared__ char smem[];
    const uint32_t sb = smem_u32(smem);
    __shared__ float s_s2[TILE_N];
    __shared__ float spv[TILE_M][4];

    const int tid = threadIdx.x, wid = tid >> 5, lane = tid & 31;
    const int warp_m = wid & 3, warp_n = wid >> 2;
    const int n0 = blockIdx.x * TILE_N, m0 = blockIdx.y * TILE_M;

    if (tid < TILE_N) s_s2[tid] = g_s2[n0 + tid];

    const char* gA = (const char*)g_A + (size_t)m0 * GROWB;
    const char* gB = (const char*)g_B + (size_t)n0 * GROWB;

    auto load_chunk = [&](int kc, int stg) {
        uint32_t sA = sb + stg * STAGE_BYTES;
        uint32_t sB = sA + A_STAGE;
        size_t colb = (size_t)kc * ROWB;
        #pragma unroll
        for (int i = 0; i < 2; i++) {
            int idx = tid + i * NTHREADS;
            int r = idx >> 3, p = (idx & 7) * 16;
            cp16(sA + swz(r, p), gA + (size_t)r * GROWB + colb + p);
        }
        #pragma unroll
        for (int i = 0; i < 4; i++) {
            int idx = tid + i * NTHREADS;
            int r = idx >> 3, p = (idx & 7) * 16;
            cp16(sB + swz(r, p), gB + (size_t)r * GROWB + colb + p);
        }
        cp_commit();
    };

    float acc[2][8][4];
    #pragma unroll
    for (int mt = 0; mt < 2; mt++)
        #pragma unroll
        for (int nb = 0; nb < 8; nb++)
            #pragma unroll
            for (int i = 0; i < 4; i++) acc[mt][nb][i] = 0.f;

    const uint32_t a_row = (uint32_t)(warp_m * 32 + (lane & 15));
    const uint32_t a_sub = (uint32_t)((lane >> 4) * 16);
    const uint32_t b_row = (uint32_t)(warp_n * 64 + (lane & 7) + ((lane >> 4) << 3));
    const uint32_t b_sub = (uint32_t)(((lane >> 3) & 1) * 16);

    load_chunk(0, 0);
    load_chunk(1, 1);
    load_chunk(2, 2);

    for (int k = 0; k < NKCH; k++) {
        if (k < NKCH - 2)       cp_wait<2>();
        else if (k == NKCH - 2) cp_wait<1>();
        else                    cp_wait<0>();
        __syncthreads();
        if (k + 3 < NKCH) load_chunk(k + 3, (k + 3) & 3);

        uint32_t sA = sb + (k & 3) * STAGE_BYTES;
        uint32_t sB = sA + A_STAGE;
        #pragma unroll
        for (int ks = 0; ks < 4; ks++) {
            uint32_t colA = (uint32_t)(ks * 32) + a_sub;
            uint32_t colB = (uint32_t)(ks * 32) + b_sub;
            uint32_t a[2][4], b[8][2];
            #pragma unroll
            for (int mt = 0; mt < 2; mt++)
                ldsm4(a[mt][0], a[mt][1], a[mt][2], a[mt][3],
                      sA + swz(a_row + mt * 16, colA));
            #pragma unroll
            for (int nb2 = 0; nb2 < 4; nb2++)
                ldsm4(b[nb2 * 2][0], b[nb2 * 2][1],
                      b[nb2 * 2 + 1][0], b[nb2 * 2 + 1][1],
                      sB + swz(b_row + nb2 * 16, colB));
            #pragma unroll
            for (int mt = 0; mt < 2; mt++)
                #pragma unroll
                for (int nb = 0; nb < 8; nb++)
                    mma16816(acc[mt][nb], a[mt], b[nb]);
        }
    }
    __syncthreads();   // all warps done with pipeline SMEM; reuse as staging

    // Epilogue: score = s2 - 2*dot -> bf16x2 into padded SMEM staging + min
    uint32_t* stg = (uint32_t*)smem;
    float bv[2][2] = {{FLT_MAX, FLT_MAX}, {FLT_MAX, FLT_MAX}};
    #pragma unroll
    for (int mt = 0; mt < 2; mt++)
        #pragma unroll
        for (int rh = 0; rh < 2; rh++) {
            int row = warp_m * 32 + mt * 16 + rh * 8 + (lane >> 2);
            #pragma unroll
            for (int nb = 0; nb < 8; nb++) {
                int col = warp_n * 64 + nb * 8 + 2 * (lane & 3);
                float sc0 = fmaf(-2.0f, acc[mt][nb][rh * 2 + 0], s_s2[col]);
                float sc1 = fmaf(-2.0f, acc[mt][nb][rh * 2 + 1], s_s2[col + 1]);
                __nv_bfloat162 p2 = __float22bfloat162_rn(make_float2(sc0, sc1));
                stg[row * SROWW + (col >> 1)] = *(uint32_t*)&p2;
                float m = fminf(sc0, sc1);
                if (m < bv[mt][rh]) bv[mt][rh] = m;
            }
        }
    __syncthreads();

    // Coalesced copy-out: 128 rows x 512 B (bf16), full-sector stores
    #pragma unroll
    for (int i = 0; i < 8; i++) {
        int idx = tid + i * NTHREADS;           // 0..4095 16B-units
        int row = idx >> 5, u = idx & 31;
        uint4 v = *(const uint4*)(smem + row * (SROWW * 4) + u * 16);
        *(uint4*)((char*)g_score + ((size_t)(m0 + row) * N_S + n0) * 2 + u * 16) = v;
    }

    // per-(q,tile) min partials
    #pragma unroll
    for (int mt = 0; mt < 2; mt++)
        #pragma unroll
        for (int rh = 0; rh < 2; rh++) {
            float v = bv[mt][rh];
            #pragma unroll
            for (int msk = 1; msk <= 2; msk <<= 1)
                v = fminf(v, __shfl_xor_sync(0xffffffffu, v, msk));
            if ((lane & 3) == 0) {
                int row = warp_m * 32 + mt * 16 + rh * 8 + (lane >> 2);
                spv[row][warp_n] = v;
            }
        }
    __syncthreads();

    if (tid < TILE_M) {
        float v = fminf(fminf(spv[tid][0], spv[tid][1]),
                        fminf(spv[tid][2], spv[tid][3]));
        g_pv[(size_t)(m0 + tid) * GRID_N + blockIdx.x] = v;
    }
}

// ---------------------------------------------------------------------------
// Reduce: global approx min per query; block 0 also detects label storage
// ---------------------------------------------------------------------------
__global__ void reduce_kernel(const int* __restrict__ lab32) {
    __shared__ float sv[GRID_N];
    const int b = blockIdx.x, t = threadIdx.x;
    sv[t] = g_pv[(size_t)b * GRID_N + t];
    __syncthreads();
    #pragma unroll
    for (int s = GRID_N / 2; s > 0; s >>= 1) {
        if (t < s) sv[t] = fminf(sv[t], sv[t + s]);
        __syncthreads();
    }
    if (t == 0) {
        g_amin[b] = sv[0];
        if (b == 0) {
            int hiOr = 0;
            #pragma unroll
            for (int w = 1; w < 64; w += 2) hiOr |= lab32[w];
            g_labmode = (hiOr == 0) ? 1 : 0;   // 1 = int64 storage
        }
    }
}

// ---------------------------------------------------------------------------
// Phase B: warp-per-query. Read 128 tile-mins; only tiles with tmin<=thresh
// get their 256 bf16 scores read; candidates rescored exactly in fp32.
// Margin covers GEMM error (2E ~ 2^-7*||x||*ymax) + bf16 storage (~1.4) + slack.
// ---------------------------------------------------------------------------
__global__ __launch_bounds__(256)
void scan_kernel(const float* __restrict__ x, const float* __restrict__ sup,
                 const int* __restrict__ lab32, float* __restrict__ out) {
    const int wid = threadIdx.x >> 5, lane = threadIdx.x & 31;
    const int q = blockIdx.x * 8 + wid;

    const float4* xrow = (const float4*)(x + (size_t)q * D_K);
    float4 xv0 = xrow[lane];
    float4 xv1 = xrow[lane + 32];

    float ymax2 = __int_as_float(g_ymax2_bits);
    float thresh = g_amin[q] + 0.03f * sqrtf(g_xs2[q] * ymax2) + 2.5f;

    float bestV = FLT_MAX; int bestN = 0;

    #pragma unroll
    for (int t = 0; t < GRID_N / 32; t++) {
        float tm = g_pv[(size_t)q * GRID_N + t * 32 + lane];
        unsigned tb = __ballot_sync(0xffffffffu, tm <= thresh);
        while (tb) {
            int tl = t * 32 + (__ffs(tb) - 1); tb &= tb - 1;
            // read this tile's 256 bf16 scores (512 B, 16 B per lane)
            const char* srow = (const char*)g_score + ((size_t)q * N_S + tl * 256) * 2;
            uint4 w = *(const uint4*)(srow + lane * 16);
            unsigned m = 0;
            const uint32_t ws[4] = {w.x, w.y, w.z, w.w};
            #pragma unroll
            for (int j = 0; j < 4; j++) {
                float2 f2 = __bfloat1622float2(*(const __nv_bfloat162*)&ws[j]);
                if (f2.x <= thresh) m |= 1u << (2 * j);
                if (f2.y <= thresh) m |= 1u << (2 * j + 1);
            }
            unsigned bal = __ballot_sync(0xffffffffu, m != 0);
            while (bal) {
                int src = __ffs(bal) - 1; bal &= bal - 1;
                unsigned mm = __shfl_sync(0xffffffffu, m, src);
                #pragma unroll
                for (int c = 0; c < 8; c++) {
                    if (mm & (1u << c)) {
                        int n = tl * 256 + src * 8 + c;
                        const float4* yrow = (const float4*)(sup + (size_t)n * D_K);
                        float4 y0 = yrow[lane], y1 = yrow[lane + 32];
                        float d = xv0.x * y0.x + xv0.y * y0.y + xv0.z * y0.z + xv0.w * y0.w
                                + xv1.x * y1.x + xv1.y * y1.y + xv1.z * y1.z + xv1.w * y1.w;
                        #pragma unroll
                        for (int off = 16; off > 0; off >>= 1)
                            d += __shfl_xor_sync(0xffffffffu, d, off);
                        float sc = g_s2[n] - 2.0f * d;
                        if (sc < bestV || (sc == bestV && n < bestN)) { bestV = sc; bestN = n; }
                    }
                }
            }
        }
    }

    // label gather (bestV/bestN uniform across warp) + one-hot
    int lbl = (g_labmode == 1) ? lab32[2 * bestN] : lab32[bestN];
    #pragma unroll
    for (int c = lane; c < N_CLS; c += 32)
        out[(size_t)q * N_CLS + c] = (c == lbl) ? 1.0f : 0.0f;
}

// ---------------------------------------------------------------------------
extern "C" void kernel_launch(void* const* d_in, const int* in_sizes, int n_in,
                              void* d_out, int out_size) {
    const float* x     = nullptr;
    const float* sup   = nullptr;
    const int*   lab32 = nullptr;
    for (int i = 0; i < n_in; i++) {
        long long sz = in_sizes[i];
        if (sz == 524288LL || sz == 2097152LL)         x     = (const float*)d_in[i];
        else if (sz == 8388608LL || sz == 33554432LL)  sup   = (const float*)d_in[i];
        else if (sz == 32768LL || sz == 65536LL ||
                 sz == 131072LL || sz == 262144LL)     lab32 = (const int*)d_in[i];
    }
    if (!x)     x     = (const float*)d_in[0];
    if (!sup)   sup   = (const float*)d_in[1];
    if (!lab32) lab32 = (const int*)d_in[2];
    float* out = (float*)d_out;

    static bool attr_set = false;
    if (!attr_set) {
        cudaFuncSetAttribute(knn_approx_kernel,
                             cudaFuncAttributeMaxDynamicSharedMemorySize,
                             STAGES * STAGE_BYTES);
        attr_set = true;
    }

    convert_x_kernel<<<B_Q, D_K>>>(x);
    convert_s_kernel<<<N_S, D_K>>>(sup);

    dim3 grid(GRID_N, GRID_M);   // 128 x 16
    knn_approx_kernel<<<grid, NTHREADS, STAGES * STAGE_BYTES>>>();

    reduce_kernel<<<B_Q, GRID_N>>>(lab32);

    scan_kernel<<<B_Q / 8, 256>>>(x, sup, lab32, out);
}